// round 4
// baseline (speedup 1.0000x reference)
#include <cuda_runtime.h>

#define BB   2
#define SS   2048
#define DD   1024
#define HH   16
#define KVHn 4
#define HD   64
#define WIN  64
#define MM   (BB*SS)   // 4096

// Scratch (allocation-free rule: __device__ globals)
__device__ float g_q[MM * HH * HD];     // [b*S+s][h*64+d] after RoPE
__device__ float g_k[MM * KVHn * HD];   // [b*S+s][kvh*64+d] after RoPE
__device__ float g_v[MM * KVHn * HD];
__device__ float g_att[MM * HH * HD];   // attention output before Wo

// ---------------------------------------------------------------------------
// Kernel 1: fused QKV projection + RoPE epilogue.
// C[4096,1536] = x[4096,1024] @ [wq | wk | wv], 64x64 block tile, BK=16,
// 256 threads, 4x4 micro-tile. Smem row stride 68 floats (272B, 16B-aligned,
// 68 % 32 == 4 -> conflict-free transposed STS of the A tile).
// ---------------------------------------------------------------------------
__global__ __launch_bounds__(256) void qkv_rope_kernel(
    const float* __restrict__ x,  const float* __restrict__ wq,
    const float* __restrict__ wk, const float* __restrict__ wv,
    const float* __restrict__ fc, const float* __restrict__ fs)
{
    __shared__ float As[16 * 68];
    __shared__ float Bs[16 * 68];
    const int tid = threadIdx.x;
    const int tx = tid & 15, ty = tid >> 4;
    const int m0 = blockIdx.y * 64;
    const int n0 = blockIdx.x * 64;

    // Whole 64-wide N tile lives in exactly one of wq/wk/wv (segment bounds
    // 1024 and 1280 are 64-aligned).
    const float* bsrc; int ldb, boff;
    if (n0 < 1024)      { bsrc = wq; ldb = 1024; boff = n0; }
    else if (n0 < 1280) { bsrc = wk; ldb = 256;  boff = n0 - 1024; }
    else                { bsrc = wv; ldb = 256;  boff = n0 - 1280; }

    const int ar = tid >> 2, ak = (tid & 3) * 4;   // A tile: 64 rows x 4 float4
    const int bk = tid >> 4, bn = (tid & 15) * 4;  // B tile: 16 rows x 16 float4

    float acc[4][4];
    #pragma unroll
    for (int i = 0; i < 4; i++)
        #pragma unroll
        for (int j = 0; j < 4; j++) acc[i][j] = 0.f;

    for (int k0 = 0; k0 < 1024; k0 += 16) {
        float4 av = *(const float4*)&x[(m0 + ar) * 1024 + k0 + ak];
        As[(ak + 0) * 68 + ar] = av.x;
        As[(ak + 1) * 68 + ar] = av.y;
        As[(ak + 2) * 68 + ar] = av.z;
        As[(ak + 3) * 68 + ar] = av.w;
        *(float4*)&Bs[bk * 68 + bn] =
            *(const float4*)&bsrc[(k0 + bk) * ldb + boff + bn];
        __syncthreads();
        #pragma unroll
        for (int kk = 0; kk < 16; ++kk) {
            float4 a = *(const float4*)&As[kk * 68 + ty * 4];
            float4 b = *(const float4*)&Bs[kk * 68 + tx * 4];
            float av4[4] = {a.x, a.y, a.z, a.w};
            float bv4[4] = {b.x, b.y, b.z, b.w};
            #pragma unroll
            for (int i = 0; i < 4; i++)
                #pragma unroll
                for (int j = 0; j < 4; j++)
                    acc[i][j] += av4[i] * bv4[j];
        }
        __syncthreads();
    }

    // Epilogue: RoPE on q/k column pairs (thread owns 4 consecutive cols,
    // 2 rope pairs), plain store for v.
    #pragma unroll
    for (int r = 0; r < 4; r++) {
        int row = m0 + ty * 4 + r;
        int s = row & (SS - 1);
        #pragma unroll
        for (int cp = 0; cp < 2; cp++) {
            float a  = acc[r][cp * 2];
            float b2 = acc[r][cp * 2 + 1];
            int n = n0 + tx * 4 + cp * 2;
            if (n < 1024) {
                int d = n & 63, j = d >> 1;
                float c = fc[s * 32 + j], sn = fs[s * 32 + j];
                g_q[row * 1024 + n]     = a * c  - b2 * sn;
                g_q[row * 1024 + n + 1] = a * sn + b2 * c;
            } else if (n < 1280) {
                int nn = n - 1024, d = nn & 63, j = d >> 1;
                float c = fc[s * 32 + j], sn = fs[s * 32 + j];
                g_k[row * 256 + nn]     = a * c  - b2 * sn;
                g_k[row * 256 + nn + 1] = a * sn + b2 * c;
            } else {
                int nn = n - 1280;
                g_v[row * 256 + nn]     = a;
                g_v[row * 256 + nn + 1] = b2;
            }
        }
    }
}

// ---------------------------------------------------------------------------
// Kernel 2: sliding-window attention.
// Block = (b, kvh, 16-query tile). K/V window (<=80 rows) in smem, shared by
// all 4 GQA rep-heads. 2 threads per (query, head): each owns half of HD.
// Online softmax; lane-pair shfl combines the two half-dot-products.
// ---------------------------------------------------------------------------
__global__ __launch_bounds__(128) void attn_kernel()
{
    __shared__ float Ks[80 * 68];
    __shared__ float Vs[80 * 68];
    const int b   = blockIdx.z;
    const int kvh = blockIdx.y;
    const int qbase  = blockIdx.x * 16;
    const int kstart = max(0, qbase - WIN);
    const int nrows  = qbase + 16 - kstart;    // <= 80
    const int tid = threadIdx.x;

    for (int i = tid; i < nrows * 16; i += 128) {
        int row = i >> 4, c = (i & 15) * 4;
        int gidx = ((b * SS + kstart + row) * KVHn + kvh) * 64 + c;
        *(float4*)&Ks[row * 68 + c] = *(const float4*)&g_k[gidx];
        *(float4*)&Vs[row * 68 + c] = *(const float4*)&g_v[gidx];
    }
    __syncthreads();

    const int half = tid & 1, pair = tid >> 1;
    const int rep = pair & 3, qi = pair >> 2;
    const int qg = qbase + qi;
    const int h  = kvh * 4 + rep;              // q-head h uses kv-head h/4
    // Pair-scoped shfl mask: the two half-threads of a (query,head) are
    // always converged; full-warp mask would be illegal (per-query loop trip
    // counts differ inside a warp).
    const unsigned pmask = 3u << ((tid & 31) & ~1);

    float qreg[32];
    const float* qp = &g_q[((b * SS + qg) * HH + h) * 64 + half * 32];
    #pragma unroll
    for (int d = 0; d < 32; d++) qreg[d] = qp[d];

    float accv[32];
    #pragma unroll
    for (int d = 0; d < 32; d++) accv[d] = 0.f;
    float m = -1e30f, l = 0.f;

    const int j0 = max(0, qg - WIN) - kstart;
    const int j1 = qg - kstart;
    for (int j = j0; j <= j1; ++j) {
        const float* kr = &Ks[j * 68 + half * 32];
        float partial = 0.f;
        #pragma unroll
        for (int d = 0; d < 32; d++) partial += qreg[d] * kr[d];
        float sc = (partial + __shfl_xor_sync(pmask, partial, 1)) * 0.125f;
        float mn  = fmaxf(m, sc);
        float esc = __expf(m - mn);
        float p   = __expf(sc - mn);
        l = l * esc + p;
        const float* vr = &Vs[j * 68 + half * 32];
        #pragma unroll
        for (int d = 0; d < 32; d++) accv[d] = accv[d] * esc + p * vr[d];
        m = mn;
    }
    float inv = 1.f / l;
    float* op = &g_att[(b * SS + qg) * 1024 + h * 64 + half * 32];
    #pragma unroll
    for (int d = 0; d < 32; d++) op[d] = accv[d] * inv;
}

// ---------------------------------------------------------------------------
// Kernel 3: output projection. out[4096,1024] = g_att @ wo. Same SGEMM.
// ---------------------------------------------------------------------------
__global__ __launch_bounds__(256) void oproj_kernel(
    const float* __restrict__ wo, float* __restrict__ out)
{
    __shared__ float As[16 * 68];
    __shared__ float Bs[16 * 68];
    const int tid = threadIdx.x;
    const int tx = tid & 15, ty = tid >> 4;
    const int m0 = blockIdx.y * 64;
    const int n0 = blockIdx.x * 64;

    const int ar = tid >> 2, ak = (tid & 3) * 4;
    const int bk = tid >> 4, bn = (tid & 15) * 4;

    float acc[4][4];
    #pragma unroll
    for (int i = 0; i < 4; i++)
        #pragma unroll
        for (int j = 0; j < 4; j++) acc[i][j] = 0.f;

    for (int k0 = 0; k0 < 1024; k0 += 16) {
        float4 av = *(const float4*)&g_att[(m0 + ar) * 1024 + k0 + ak];
        As[(ak + 0) * 68 + ar] = av.x;
        As[(ak + 1) * 68 + ar] = av.y;
        As[(ak + 2) * 68 + ar] = av.z;
        As[(ak + 3) * 68 + ar] = av.w;
        *(float4*)&Bs[bk * 68 + bn] =
            *(const float4*)&wo[(k0 + bk) * 1024 + n0 + bn];
        __syncthreads();
        #pragma unroll
        for (int kk = 0; kk < 16; ++kk) {
            float4 a = *(const float4*)&As[kk * 68 + ty * 4];
            float4 b = *(const float4*)&Bs[kk * 68 + tx * 4];
            float av4[4] = {a.x, a.y, a.z, a.w};
            float bv4[4] = {b.x, b.y, b.z, b.w};
            #pragma unroll
            for (int i = 0; i < 4; i++)
                #pragma unroll
                for (int j = 0; j < 4; j++)
                    acc[i][j] += av4[i] * bv4[j];
        }
        __syncthreads();
    }

    #pragma unroll
    for (int r = 0; r < 4; r++) {
        int row = m0 + ty * 4 + r;
        #pragma unroll
        for (int j = 0; j < 4; j++)
            out[row * 1024 + n0 + tx * 4 + j] = acc[r][j];
    }
}

// ---------------------------------------------------------------------------
extern "C" void kernel_launch(void* const* d_in, const int* in_sizes, int n_in,
                              void* d_out, int out_size)
{
    const float* x  = (const float*)d_in[0];
    const float* fc = (const float*)d_in[1];
    const float* fs = (const float*)d_in[2];
    const float* wq = (const float*)d_in[3];
    const float* wk = (const float*)d_in[4];
    const float* wv = (const float*)d_in[5];
    const float* wo = (const float*)d_in[6];
    float* out = (float*)d_out;

    qkv_rope_kernel<<<dim3(24, 64), 256>>>(x, wq, wk, wv, fc, fs);
    attn_kernel<<<dim3(SS / 16, KVHn, BB), 128>>>();
    oproj_kernel<<<dim3(16, 64), 256>>>(wo, out);
}

// round 5
// speedup vs baseline: 1.2326x; 1.2326x over previous
#include <cuda_runtime.h>

#define BB   2
#define SS   2048
#define DD   1024
#define HH   16
#define KVHn 4
#define HD   64
#define WIN  64
#define MM   (BB*SS)   // 4096

typedef unsigned long long ull;

// packed f32x2 helpers (FFMA2 path — ptxas never emits it from plain C++)
#define PACK2(d, x, y)  asm("mov.b64 %0, {%1, %2};" : "=l"(d) : "f"(x), "f"(y))
#define DUP2(d, x)      asm("mov.b64 %0, {%1, %1};" : "=l"(d) : "f"(x))
#define UNPACK2(lo, hi, d) asm("mov.b64 {%0, %1}, %2;" : "=f"(lo), "=f"(hi) : "l"(d))
#define FMA2(d, a, b)   asm("fma.rn.f32x2 %0, %1, %2, %0;" : "+l"(d) : "l"(a), "l"(b))
#define MUL2(d, a, b)   asm("mul.rn.f32x2 %0, %1, %2;" : "=l"(d) : "l"(a), "l"(b))
#define ADD2(d, a, b)   asm("add.rn.f32x2 %0, %1, %2;" : "=l"(d) : "l"(a), "l"(b))

// Scratch (allocation-free rule: __device__ globals)
__device__ float g_q[MM * HH * HD];
__device__ float g_k[MM * KVHn * HD];
__device__ float g_v[MM * KVHn * HD];
__device__ float g_att[MM * HH * HD];

// ---------------------------------------------------------------------------
// Kernel 1: fused QKV projection + RoPE. 128x128x16 tiles, 256 threads,
// 8x8 micro-tile computed as 4 row-pairs x 8 cols in packed f32x2 (FFMA2).
// Smem row stride 132 floats (16B-aligned for float4 LDS).
// ---------------------------------------------------------------------------
__global__ __launch_bounds__(256, 2) void qkv_rope_kernel(
    const float* __restrict__ x,  const float* __restrict__ wq,
    const float* __restrict__ wk, const float* __restrict__ wv,
    const float* __restrict__ fc, const float* __restrict__ fs)
{
    __shared__ float As[16 * 132];   // transposed: As[k][m]
    __shared__ float Bs[16 * 132];   // Bs[k][n]
    const int tid = threadIdx.x;
    const int tx = tid & 15, ty = tid >> 4;
    const int m0 = blockIdx.y * 128;
    const int n0 = blockIdx.x * 128;

    // Whole 128-wide N tile lives in exactly one of wq/wk/wv (bounds 1024 and
    // 1280 are 128-aligned... 1280-1024=256=2 tiles, 1536-1280=256).
    const float* bsrc; int ldb, boff;
    if (n0 < 1024)      { bsrc = wq; ldb = 1024; boff = n0; }
    else if (n0 < 1280) { bsrc = wk; ldb = 256;  boff = n0 - 1024; }
    else                { bsrc = wv; ldb = 256;  boff = n0 - 1280; }

    const int ar = tid >> 2, ak = (tid & 3) * 4;   // A: 2 float4/thread
    const int bk = tid >> 4, bn = (tid & 15) * 4;  // B: 2 float4/thread

    ull acc2[4][8];
    #pragma unroll
    for (int i = 0; i < 4; i++)
        #pragma unroll
        for (int j = 0; j < 8; j++) acc2[i][j] = 0ULL;

    float4 a_pre[2], b_pre[2];
    a_pre[0] = *(const float4*)&x[(m0 + ar) * 1024 + ak];
    a_pre[1] = *(const float4*)&x[(m0 + ar + 64) * 1024 + ak];
    b_pre[0] = *(const float4*)&bsrc[bk * ldb + boff + bn];
    b_pre[1] = *(const float4*)&bsrc[bk * ldb + boff + bn + 64];

    for (int k0 = 0; k0 < 1024; k0 += 16) {
        // stage current tile
        #pragma unroll
        for (int i = 0; i < 2; i++) {
            int row = ar + i * 64;
            As[(ak + 0) * 132 + row] = a_pre[i].x;
            As[(ak + 1) * 132 + row] = a_pre[i].y;
            As[(ak + 2) * 132 + row] = a_pre[i].z;
            As[(ak + 3) * 132 + row] = a_pre[i].w;
            *(float4*)&Bs[bk * 132 + bn + i * 64] = b_pre[i];
        }
        __syncthreads();

        // prefetch next tile (overlaps compute)
        if (k0 + 16 < 1024) {
            a_pre[0] = *(const float4*)&x[(m0 + ar) * 1024 + k0 + 16 + ak];
            a_pre[1] = *(const float4*)&x[(m0 + ar + 64) * 1024 + k0 + 16 + ak];
            b_pre[0] = *(const float4*)&bsrc[(k0 + 16 + bk) * ldb + boff + bn];
            b_pre[1] = *(const float4*)&bsrc[(k0 + 16 + bk) * ldb + boff + bn + 64];
        }

        #pragma unroll
        for (int kk = 0; kk < 16; ++kk) {
            const float4 a0 = *(const float4*)&As[kk * 132 + ty * 8];
            const float4 a1 = *(const float4*)&As[kk * 132 + ty * 8 + 4];
            const float4 b0 = *(const float4*)&Bs[kk * 132 + tx * 8];
            const float4 b1 = *(const float4*)&Bs[kk * 132 + tx * 8 + 4];
            ull A2[4], B2[8];
            PACK2(A2[0], a0.x, a0.y); PACK2(A2[1], a0.z, a0.w);
            PACK2(A2[2], a1.x, a1.y); PACK2(A2[3], a1.z, a1.w);
            DUP2(B2[0], b0.x); DUP2(B2[1], b0.y);
            DUP2(B2[2], b0.z); DUP2(B2[3], b0.w);
            DUP2(B2[4], b1.x); DUP2(B2[5], b1.y);
            DUP2(B2[6], b1.z); DUP2(B2[7], b1.w);
            #pragma unroll
            for (int i = 0; i < 4; i++)
                #pragma unroll
                for (int j = 0; j < 8; j++)
                    FMA2(acc2[i][j], A2[i], B2[j]);
        }
        __syncthreads();
    }

    // unpack: C[r][j], r = 2*ip + half (8 consecutive rows), j = 8 cols
    float C[8][8];
    #pragma unroll
    for (int ip = 0; ip < 4; ip++)
        #pragma unroll
        for (int j = 0; j < 8; j++)
            UNPACK2(C[2 * ip][j], C[2 * ip + 1][j], acc2[ip][j]);

    float* dst; int ld, cb; bool rope;
    if (n0 < 1024)      { dst = g_q; ld = 1024; cb = n0;        rope = true;  }
    else if (n0 < 1280) { dst = g_k; ld = 256;  cb = n0 - 1024; rope = true;  }
    else                { dst = g_v; ld = 256;  cb = n0 - 1280; rope = false; }
    const int col0  = cb + tx * 8;
    const int jbase = ((tx * 8) & 63) >> 1;   // rope freq index base

    #pragma unroll
    for (int r = 0; r < 8; r++) {
        const int row = m0 + ty * 8 + r;
        const int s   = row & (SS - 1);
        float o[8];
        if (rope) {
            #pragma unroll
            for (int cp = 0; cp < 4; cp++) {
                float c  = fc[s * 32 + jbase + cp];
                float sn = fs[s * 32 + jbase + cp];
                float a  = C[r][2 * cp];
                float b  = C[r][2 * cp + 1];
                o[2 * cp]     = a * c  - b * sn;
                o[2 * cp + 1] = a * sn + b * c;
            }
        } else {
            #pragma unroll
            for (int j = 0; j < 8; j++) o[j] = C[r][j];
        }
        *(float4*)&dst[row * ld + col0]     = make_float4(o[0], o[1], o[2], o[3]);
        *(float4*)&dst[row * ld + col0 + 4] = make_float4(o[4], o[5], o[6], o[7]);
    }
}

// ---------------------------------------------------------------------------
// Kernel 2: sliding-window attention, f32x2-vectorized online softmax.
// Block = (b, kvh, 16-query tile). K/V window (<=80 rows) in smem, shared by
// all 4 GQA rep-heads. 2 threads per (query, head); lane-pair shfl combine.
// Accumulator rescale branch-skipped when running max unchanged.
// ---------------------------------------------------------------------------
__global__ __launch_bounds__(128) void attn_kernel()
{
    __shared__ float Ks[80 * 68];
    __shared__ float Vs[80 * 68];
    const int b   = blockIdx.z;
    const int kvh = blockIdx.y;
    const int qbase  = blockIdx.x * 16;
    const int kstart = max(0, qbase - WIN);
    const int nrows  = qbase + 16 - kstart;    // <= 80
    const int tid = threadIdx.x;

    for (int i = tid; i < nrows * 16; i += 128) {
        int row = i >> 4, c = (i & 15) * 4;
        int gidx = ((b * SS + kstart + row) * KVHn + kvh) * 64 + c;
        *(float4*)&Ks[row * 68 + c] = *(const float4*)&g_k[gidx];
        *(float4*)&Vs[row * 68 + c] = *(const float4*)&g_v[gidx];
    }
    __syncthreads();

    const int half = tid & 1, pair = tid >> 1;
    const int rep = pair & 3, qi = pair >> 2;
    const int qg = qbase + qi;
    const int h  = kvh * 4 + rep;
    // pair-scoped shfl mask (per-query trip counts differ inside a warp)
    const unsigned pmask = 3u << ((tid & 31) & ~1);

    ull q2[16];
    {
        const float4* qp = (const float4*)&g_q[((b * SS + qg) * HH + h) * 64 + half * 32];
        #pragma unroll
        for (int t = 0; t < 8; t++) {
            float4 v = qp[t];
            PACK2(q2[2 * t],     v.x, v.y);
            PACK2(q2[2 * t + 1], v.z, v.w);
        }
    }

    ull acc2[16];
    #pragma unroll
    for (int d = 0; d < 16; d++) acc2[d] = 0ULL;
    float m = -1e30f, l = 0.f;

    const int j0 = max(0, qg - WIN) - kstart;
    const int j1 = qg - kstart;
    for (int j = j0; j <= j1; ++j) {
        // dot(q, k) over this thread's 32 dims, 4-way split accumulators
        const float4* kr = (const float4*)&Ks[j * 68 + half * 32];
        ull d2[4] = {0ULL, 0ULL, 0ULL, 0ULL};
        #pragma unroll
        for (int t = 0; t < 8; t++) {
            float4 kv = kr[t];
            ull k2a, k2b;
            PACK2(k2a, kv.x, kv.y);
            PACK2(k2b, kv.z, kv.w);
            FMA2(d2[(2 * t) & 3],     q2[2 * t],     k2a);
            FMA2(d2[(2 * t + 1) & 3], q2[2 * t + 1], k2b);
        }
        ull s01, s23, sall;
        ADD2(s01, d2[0], d2[1]);
        ADD2(s23, d2[2], d2[3]);
        ADD2(sall, s01, s23);
        float plo, phi;
        UNPACK2(plo, phi, sall);
        float partial = plo + phi;
        float sc = (partial + __shfl_xor_sync(pmask, partial, 1)) * 0.125f;

        if (sc > m) {                       // rare after warm-up (~log W times)
            float esc = __expf(m - sc);
            ull esc2; DUP2(esc2, esc);
            l *= esc;
            #pragma unroll
            for (int d = 0; d < 16; d++) { ull t2; MUL2(t2, acc2[d], esc2); acc2[d] = t2; }
            m = sc;
        }
        float p = __expf(sc - m);
        l += p;
        ull p2; DUP2(p2, p);
        const float4* vr = (const float4*)&Vs[j * 68 + half * 32];
        #pragma unroll
        for (int t = 0; t < 8; t++) {
            float4 vv = vr[t];
            ull v2a, v2b;
            PACK2(v2a, vv.x, vv.y);
            PACK2(v2b, vv.z, vv.w);
            FMA2(acc2[2 * t],     v2a, p2);
            FMA2(acc2[2 * t + 1], v2b, p2);
        }
    }

    const float inv = 1.f / l;
    float* op = &g_att[(b * SS + qg) * 1024 + h * 64 + half * 32];
    #pragma unroll
    for (int t = 0; t < 8; t++) {
        float x0, x1, x2, x3;
        UNPACK2(x0, x1, acc2[2 * t]);
        UNPACK2(x2, x3, acc2[2 * t + 1]);
        *(float4*)&op[t * 4] = make_float4(x0 * inv, x1 * inv, x2 * inv, x3 * inv);
    }
}

// ---------------------------------------------------------------------------
// Kernel 3: output projection. out[4096,1024] = g_att @ wo. Same FFMA2 SGEMM.
// ---------------------------------------------------------------------------
__global__ __launch_bounds__(256, 2) void oproj_kernel(
    const float* __restrict__ wo, float* __restrict__ out)
{
    __shared__ float As[16 * 132];
    __shared__ float Bs[16 * 132];
    const int tid = threadIdx.x;
    const int tx = tid & 15, ty = tid >> 4;
    const int m0 = blockIdx.y * 128;
    const int n0 = blockIdx.x * 128;

    const int ar = tid >> 2, ak = (tid & 3) * 4;
    const int bk = tid >> 4, bn = (tid & 15) * 4;

    ull acc2[4][8];
    #pragma unroll
    for (int i = 0; i < 4; i++)
        #pragma unroll
        for (int j = 0; j < 8; j++) acc2[i][j] = 0ULL;

    float4 a_pre[2], b_pre[2];
    a_pre[0] = *(const float4*)&g_att[(m0 + ar) * 1024 + ak];
    a_pre[1] = *(const float4*)&g_att[(m0 + ar + 64) * 1024 + ak];
    b_pre[0] = *(const float4*)&wo[bk * 1024 + n0 + bn];
    b_pre[1] = *(const float4*)&wo[bk * 1024 + n0 + bn + 64];

    for (int k0 = 0; k0 < 1024; k0 += 16) {
        #pragma unroll
        for (int i = 0; i < 2; i++) {
            int row = ar + i * 64;
            As[(ak + 0) * 132 + row] = a_pre[i].x;
            As[(ak + 1) * 132 + row] = a_pre[i].y;
            As[(ak + 2) * 132 + row] = a_pre[i].z;
            As[(ak + 3) * 132 + row] = a_pre[i].w;
            *(float4*)&Bs[bk * 132 + bn + i * 64] = b_pre[i];
        }
        __syncthreads();

        if (k0 + 16 < 1024) {
            a_pre[0] = *(const float4*)&g_att[(m0 + ar) * 1024 + k0 + 16 + ak];
            a_pre[1] = *(const float4*)&g_att[(m0 + ar + 64) * 1024 + k0 + 16 + ak];
            b_pre[0] = *(const float4*)&wo[(k0 + 16 + bk) * 1024 + n0 + bn];
            b_pre[1] = *(const float4*)&wo[(k0 + 16 + bk) * 1024 + n0 + bn + 64];
        }

        #pragma unroll
        for (int kk = 0; kk < 16; ++kk) {
            const float4 a0 = *(const float4*)&As[kk * 132 + ty * 8];
            const float4 a1 = *(const float4*)&As[kk * 132 + ty * 8 + 4];
            const float4 b0 = *(const float4*)&Bs[kk * 132 + tx * 8];
            const float4 b1 = *(const float4*)&Bs[kk * 132 + tx * 8 + 4];
            ull A2[4], B2[8];
            PACK2(A2[0], a0.x, a0.y); PACK2(A2[1], a0.z, a0.w);
            PACK2(A2[2], a1.x, a1.y); PACK2(A2[3], a1.z, a1.w);
            DUP2(B2[0], b0.x); DUP2(B2[1], b0.y);
            DUP2(B2[2], b0.z); DUP2(B2[3], b0.w);
            DUP2(B2[4], b1.x); DUP2(B2[5], b1.y);
            DUP2(B2[6], b1.z); DUP2(B2[7], b1.w);
            #pragma unroll
            for (int i = 0; i < 4; i++)
                #pragma unroll
                for (int j = 0; j < 8; j++)
                    FMA2(acc2[i][j], A2[i], B2[j]);
        }
        __syncthreads();
    }

    #pragma unroll
    for (int ip = 0; ip < 4; ip++) {
        float C0[8], C1[8];
        #pragma unroll
        for (int j = 0; j < 8; j++) UNPACK2(C0[j], C1[j], acc2[ip][j]);
        const int r0 = m0 + ty * 8 + 2 * ip;
        const int c0 = n0 + tx * 8;
        *(float4*)&out[r0 * 1024 + c0]           = make_float4(C0[0], C0[1], C0[2], C0[3]);
        *(float4*)&out[r0 * 1024 + c0 + 4]       = make_float4(C0[4], C0[5], C0[6], C0[7]);
        *(float4*)&out[(r0 + 1) * 1024 + c0]     = make_float4(C1[0], C1[1], C1[2], C1[3]);
        *(float4*)&out[(r0 + 1) * 1024 + c0 + 4] = make_float4(C1[4], C1[5], C1[6], C1[7]);
    }
}

// ---------------------------------------------------------------------------
extern "C" void kernel_launch(void* const* d_in, const int* in_sizes, int n_in,
                              void* d_out, int out_size)
{
    const float* x  = (const float*)d_in[0];
    const float* fc = (const float*)d_in[1];
    const float* fs = (const float*)d_in[2];
    const float* wq = (const float*)d_in[3];
    const float* wk = (const float*)d_in[4];
    const float* wv = (const float*)d_in[5];
    const float* wo = (const float*)d_in[6];
    float* out = (float*)d_out;

    qkv_rope_kernel<<<dim3(12, 32), 256>>>(x, wq, wk, wv, fc, fs);
    attn_kernel<<<dim3(SS / 16, KVHn, BB), 128>>>();
    oproj_kernel<<<dim3(8, 32), 256>>>(wo, out);
}

// round 7
// speedup vs baseline: 2.0700x; 1.6794x over previous
#include <cuda_runtime.h>
#include <cuda_bf16.h>
#include <cstdint>

#define BB   2
#define SS   2048
#define DD   1024
#define HH   16
#define KVHn 4
#define HD   64
#define WIN  64
#define MM   (BB*SS)   // 4096

typedef unsigned long long ull;

// packed f32x2 helpers (attention kernel)
#define PACK2(d, x, y)  asm("mov.b64 %0, {%1, %2};" : "=l"(d) : "f"(x), "f"(y))
#define DUP2(d, x)      asm("mov.b64 %0, {%1, %1};" : "=l"(d) : "f"(x))
#define UNPACK2(lo, hi, d) asm("mov.b64 {%0, %1}, %2;" : "=f"(lo), "=f"(hi) : "l"(d))
#define FMA2(d, a, b)   asm("fma.rn.f32x2 %0, %1, %2, %0;" : "+l"(d) : "l"(a), "l"(b))
#define MUL2(d, a, b)   asm("mul.rn.f32x2 %0, %1, %2;" : "=l"(d) : "l"(a), "l"(b))
#define ADD2(d, a, b)   asm("add.rn.f32x2 %0, %1, %2;" : "=l"(d) : "l"(a), "l"(b))

__device__ __forceinline__ uint32_t smem_u32(const void* p) {
    uint32_t a;
    asm("{ .reg .u64 t; cvta.to.shared.u64 t, %1; cvt.u32.u64 %0, t; }"
        : "=r"(a) : "l"(p));
    return a;
}

// warp-level tensor core ops (no sm_103a-only instructions!)
__device__ __forceinline__ void ldsm4(uint32_t* r, uint32_t addr) {
    asm volatile("ldmatrix.sync.aligned.m8n8.x4.shared.b16 {%0,%1,%2,%3}, [%4];"
                 : "=r"(r[0]), "=r"(r[1]), "=r"(r[2]), "=r"(r[3]) : "r"(addr));
}
__device__ __forceinline__ void mma_bf16(float* c, const uint32_t* a, const uint32_t* b) {
    asm volatile(
        "mma.sync.aligned.m16n8k16.row.col.f32.bf16.bf16.f32 "
        "{%0,%1,%2,%3}, {%4,%5,%6,%7}, {%8,%9}, {%0,%1,%2,%3};"
        : "+f"(c[0]), "+f"(c[1]), "+f"(c[2]), "+f"(c[3])
        : "r"(a[0]), "r"(a[1]), "r"(a[2]), "r"(a[3]), "r"(b[0]), "r"(b[1]));
}

// ---------------------------------------------------------------------------
// Device scratch
// ---------------------------------------------------------------------------
__device__ float g_q[MM * HH * HD];
__device__ float g_k[MM * KVHn * HD];
__device__ float g_v[MM * KVHn * HD];
__device__ __nv_bfloat16 g_xhi[MM * DD],  g_xlo[MM * DD];          // x split
__device__ __nv_bfloat16 g_wt_hi[1536 * DD], g_wt_lo[1536 * DD];   // [wq|wk|wv]^T
__device__ __nv_bfloat16 g_wo_hi[DD * DD],   g_wo_lo[DD * DD];     // wo^T
__device__ __nv_bfloat16 g_ahi[MM * DD],  g_alo[MM * DD];          // attn out split

// ---------------------------------------------------------------------------
// Split fp32 -> bf16 hi/lo (no transpose). 4 elems/thread.
// ---------------------------------------------------------------------------
__global__ __launch_bounds__(256) void split_kernel(
    const float* __restrict__ src, __nv_bfloat16* __restrict__ hi,
    __nv_bfloat16* __restrict__ lo)
{
    const int i = (blockIdx.x * 256 + threadIdx.x) * 4;
    float4 v = *(const float4*)&src[i];
    __nv_bfloat16 h0 = __float2bfloat16(v.x), h1 = __float2bfloat16(v.y);
    __nv_bfloat16 h2 = __float2bfloat16(v.z), h3 = __float2bfloat16(v.w);
    __nv_bfloat16 l0 = __float2bfloat16(v.x - __bfloat162float(h0));
    __nv_bfloat16 l1 = __float2bfloat16(v.y - __bfloat162float(h1));
    __nv_bfloat16 l2 = __float2bfloat16(v.z - __bfloat162float(h2));
    __nv_bfloat16 l3 = __float2bfloat16(v.w - __bfloat162float(h3));
    __nv_bfloat162 H[2] = {__halves2bfloat162(h0, h1), __halves2bfloat162(h2, h3)};
    __nv_bfloat162 L[2] = {__halves2bfloat162(l0, l1), __halves2bfloat162(l2, l3)};
    *(uint2*)&hi[i] = *(uint2*)H;
    *(uint2*)&lo[i] = *(uint2*)L;
}

// ---------------------------------------------------------------------------
// Transpose + split: W[1024][N] row-major -> T[rowOff+n][k] bf16 hi/lo (K=1024)
// ---------------------------------------------------------------------------
__global__ __launch_bounds__(256) void transpose_split_kernel(
    const float* __restrict__ W, int N,
    __nv_bfloat16* __restrict__ Thi, __nv_bfloat16* __restrict__ Tlo, int rowOff)
{
    __shared__ float tile[32][33];
    const int tx = threadIdx.x, ty = threadIdx.y;
    const int n0 = blockIdx.x * 32, k0 = blockIdx.y * 32;
    #pragma unroll
    for (int j = ty; j < 32; j += 8)
        tile[j][tx] = W[(k0 + j) * N + n0 + tx];
    __syncthreads();
    #pragma unroll
    for (int j = ty; j < 32; j += 8) {
        float v = tile[tx][j];
        __nv_bfloat16 h = __float2bfloat16(v);
        __nv_bfloat16 l = __float2bfloat16(v - __bfloat162float(h));
        Thi[(rowOff + n0 + j) * 1024 + k0 + tx] = h;
        Tlo[(rowOff + n0 + j) * 1024 + k0 + tx] = l;
    }
}

// ---------------------------------------------------------------------------
// HMMA GEMM: D[M,N] = A[M,1024] @ B[N,1024]^T, bf16 hi/lo 3-MMA split,
// fp32 accumulators. 128x128x32 CTA tile, 8 warps x (64x32) warp tile.
// Smem rows padded to 80B -> ldmatrix conflict-free (80*r mod 128 covers all
// eight 16B phase slots). Register prefetch overlaps gmem with MMA.
// mode 0: qkv epilogue (RoPE -> g_q/g_k/g_v); mode 1: plain fp32 -> outp.
// ---------------------------------------------------------------------------
__global__ __launch_bounds__(256) void mma_gemm_kernel(
    const __nv_bfloat16* __restrict__ Ahi, const __nv_bfloat16* __restrict__ Alo,
    const __nv_bfloat16* __restrict__ Bhi, const __nv_bfloat16* __restrict__ Blo,
    const float* __restrict__ fc, const float* __restrict__ fs,
    float* __restrict__ outp, int mode)
{
    // 4 tiles x 128 rows x 40 bf16 (32 data + 8 pad) = 40960 B static smem
    __shared__ __align__(16) __nv_bfloat16 sAh[128 * 40], sAl[128 * 40];
    __shared__ __align__(16) __nv_bfloat16 sBh[128 * 40], sBl[128 * 40];

    const int tid  = threadIdx.x;
    const int lane = tid & 31, wid = tid >> 5;
    const int wm = wid & 1, wn = wid >> 1;       // warp grid 2m x 4n
    const int m0 = blockIdx.y * 128, n0 = blockIdx.x * 128;

    // ---- gmem load mapping: thread covers one row, 32B (2 int4) ----
    const int lr = tid >> 1, lc = (tid & 1) * 16;          // row 0..127, col 0/16
    const __nv_bfloat16* pAh = &Ahi[(m0 + lr) * 1024 + lc];
    const __nv_bfloat16* pAl = &Alo[(m0 + lr) * 1024 + lc];
    const __nv_bfloat16* pBh = &Bhi[(n0 + lr) * 1024 + lc];
    const __nv_bfloat16* pBl = &Blo[(n0 + lr) * 1024 + lc];
    const int ss = lr * 40 + lc;                            // smem elem offset

    // ---- ldmatrix address bases (byte offsets into each tile) ----
    // A: lanes 0-15 rows, lanes>=16 k+8   B: (lane&7)+((lane&16)?8:0) rows, (lane&8)?k+8
    const uint32_t a_base = ((wm * 64 + (lane & 15)) * 40 + ((lane & 16) ? 8 : 0)) * 2;
    const uint32_t b_base = ((wn * 32 + (lane & 7) + ((lane & 16) ? 8 : 0)) * 40
                             + ((lane & 8) ? 8 : 0)) * 2;
    const uint32_t uAh = smem_u32(sAh) + a_base, uAl = smem_u32(sAl) + a_base;
    const uint32_t uBh = smem_u32(sBh) + b_base, uBl = smem_u32(sBl) + b_base;

    float acc[4][4][4];
    #pragma unroll
    for (int i = 0; i < 4; i++)
        #pragma unroll
        for (int j = 0; j < 4; j++)
            #pragma unroll
            for (int q = 0; q < 4; q++) acc[i][j][q] = 0.f;

    int4 pr[8];
    #define PREF(koff) do {                                   \
        pr[0] = *(const int4*)&pAh[koff];                     \
        pr[1] = *(const int4*)&pAh[(koff) + 8];               \
        pr[2] = *(const int4*)&pAl[koff];                     \
        pr[3] = *(const int4*)&pAl[(koff) + 8];               \
        pr[4] = *(const int4*)&pBh[koff];                     \
        pr[5] = *(const int4*)&pBh[(koff) + 8];               \
        pr[6] = *(const int4*)&pBl[koff];                     \
        pr[7] = *(const int4*)&pBl[(koff) + 8];               \
    } while (0)

    PREF(0);
    for (int kc = 0; kc < 32; ++kc) {
        if (kc) __syncthreads();                  // prior reads done
        *(int4*)&sAh[ss]     = pr[0];
        *(int4*)&sAh[ss + 8] = pr[1];
        *(int4*)&sAl[ss]     = pr[2];
        *(int4*)&sAl[ss + 8] = pr[3];
        *(int4*)&sBh[ss]     = pr[4];
        *(int4*)&sBh[ss + 8] = pr[5];
        *(int4*)&sBl[ss]     = pr[6];
        *(int4*)&sBl[ss + 8] = pr[7];
        __syncthreads();
        if (kc < 31) PREF((kc + 1) * 32);         // in flight during MMA

        #pragma unroll
        for (int ks = 0; ks < 2; ++ks) {          // two k16 steps per chunk
            const uint32_t kb = ks * 32;          // 16 bf16 = 32 bytes
            uint32_t Af[2][4][4];                 // [hi/lo][mt][reg]
            uint32_t Bf[2][4][2];                 // [hi/lo][nt][reg]
            #pragma unroll
            for (int mt = 0; mt < 4; mt++) {
                ldsm4(Af[0][mt], uAh + mt * 16 * 80 + kb);
                ldsm4(Af[1][mt], uAl + mt * 16 * 80 + kb);
            }
            #pragma unroll
            for (int np = 0; np < 2; np++) {
                uint32_t t[4];
                ldsm4(t, uBh + np * 16 * 80 + kb);
                Bf[0][2*np][0] = t[0]; Bf[0][2*np][1] = t[1];
                Bf[0][2*np+1][0] = t[2]; Bf[0][2*np+1][1] = t[3];
                ldsm4(t, uBl + np * 16 * 80 + kb);
                Bf[1][2*np][0] = t[0]; Bf[1][2*np][1] = t[1];
                Bf[1][2*np+1][0] = t[2]; Bf[1][2*np+1][1] = t[3];
            }
            #pragma unroll
            for (int mt = 0; mt < 4; mt++)
                #pragma unroll
                for (int nt = 0; nt < 4; nt++) {
                    mma_bf16(acc[mt][nt], Af[0][mt], Bf[0][nt]);  // hi*hi
                    mma_bf16(acc[mt][nt], Af[0][mt], Bf[1][nt]);  // hi*lo
                    mma_bf16(acc[mt][nt], Af[1][mt], Bf[0][nt]);  // lo*hi
                }
        }
    }

    // ---- epilogue ----
    const int g = lane >> 2, t2 = (lane & 3) * 2;
    float* dst; int ld, coff; bool rope;
    if (mode == 1)      { dst = outp; ld = 1024; coff = n0;        rope = false; }
    else if (n0 < 1024) { dst = g_q;  ld = 1024; coff = n0;        rope = true;  }
    else if (n0 < 1280) { dst = g_k;  ld = 256;  coff = n0 - 1024; rope = true;  }
    else                { dst = g_v;  ld = 256;  coff = n0 - 1280; rope = false; }

    #pragma unroll
    for (int mt = 0; mt < 4; mt++) {
        #pragma unroll
        for (int h2 = 0; h2 < 2; h2++) {
            const int row = m0 + wm * 64 + mt * 16 + g + h2 * 8;
            const int s   = row & (SS - 1);
            #pragma unroll
            for (int nt = 0; nt < 4; nt++) {
                const int col = wn * 32 + nt * 8 + t2;   // 0..127 in block
                float v0 = acc[mt][nt][h2 * 2];
                float v1 = acc[mt][nt][h2 * 2 + 1];
                if (rope) {
                    const int j = ((n0 + col) & 63) >> 1;
                    float c  = fc[s * 32 + j];
                    float sn = fs[s * 32 + j];
                    float o0 = v0 * c  - v1 * sn;
                    float o1 = v0 * sn + v1 * c;
                    v0 = o0; v1 = o1;
                }
                *(float2*)&dst[row * ld + coff + col] = make_float2(v0, v1);
            }
        }
    }
}

// ---------------------------------------------------------------------------
// Sliding-window attention (f32x2 online softmax; emits bf16 hi/lo).
// ---------------------------------------------------------------------------
__global__ __launch_bounds__(128) void attn_kernel()
{
    __shared__ float Ks[80 * 68];
    __shared__ float Vs[80 * 68];
    const int b   = blockIdx.z;
    const int kvh = blockIdx.y;
    const int qbase  = blockIdx.x * 16;
    const int kstart = max(0, qbase - WIN);
    const int nrows  = qbase + 16 - kstart;    // <= 80
    const int tid = threadIdx.x;

    for (int i = tid; i < nrows * 16; i += 128) {
        int row = i >> 4, c = (i & 15) * 4;
        int gidx = ((b * SS + kstart + row) * KVHn + kvh) * 64 + c;
        *(float4*)&Ks[row * 68 + c] = *(const float4*)&g_k[gidx];
        *(float4*)&Vs[row * 68 + c] = *(const float4*)&g_v[gidx];
    }
    __syncthreads();

    const int half = tid & 1, pair = tid >> 1;
    const int rep = pair & 3, qi = pair >> 2;
    const int qg = qbase + qi;
    const int h  = kvh * 4 + rep;
    const unsigned pmask = 3u << ((tid & 31) & ~1);

    ull q2[16];
    {
        const float4* qp = (const float4*)&g_q[((b * SS + qg) * HH + h) * 64 + half * 32];
        #pragma unroll
        for (int t = 0; t < 8; t++) {
            float4 v = qp[t];
            PACK2(q2[2 * t],     v.x, v.y);
            PACK2(q2[2 * t + 1], v.z, v.w);
        }
    }

    ull acc2[16];
    #pragma unroll
    for (int d = 0; d < 16; d++) acc2[d] = 0ULL;
    float m = -1e30f, l = 0.f;

    const int j0 = max(0, qg - WIN) - kstart;
    const int j1 = qg - kstart;
    for (int j = j0; j <= j1; ++j) {
        const float4* kr = (const float4*)&Ks[j * 68 + half * 32];
        ull d2[4] = {0ULL, 0ULL, 0ULL, 0ULL};
        #pragma unroll
        for (int t = 0; t < 8; t++) {
            float4 kv = kr[t];
            ull k2a, k2b;
            PACK2(k2a, kv.x, kv.y);
            PACK2(k2b, kv.z, kv.w);
            FMA2(d2[(2 * t) & 3],     q2[2 * t],     k2a);
            FMA2(d2[(2 * t + 1) & 3], q2[2 * t + 1], k2b);
        }
        ull s01, s23, sall;
        ADD2(s01, d2[0], d2[1]);
        ADD2(s23, d2[2], d2[3]);
        ADD2(sall, s01, s23);
        float plo, phi;
        UNPACK2(plo, phi, sall);
        float partial = plo + phi;
        float sc = (partial + __shfl_xor_sync(pmask, partial, 1)) * 0.125f;

        if (sc > m) {
            float esc = __expf(m - sc);
            ull esc2; DUP2(esc2, esc);
            l *= esc;
            #pragma unroll
            for (int d = 0; d < 16; d++) { ull t2; MUL2(t2, acc2[d], esc2); acc2[d] = t2; }
            m = sc;
        }
        float p = __expf(sc - m);
        l += p;
        ull p2; DUP2(p2, p);
        const float4* vr = (const float4*)&Vs[j * 68 + half * 32];
        #pragma unroll
        for (int t = 0; t < 8; t++) {
            float4 vv = vr[t];
            ull v2a, v2b;
            PACK2(v2a, vv.x, vv.y);
            PACK2(v2b, vv.z, vv.w);
            FMA2(acc2[2 * t],     v2a, p2);
            FMA2(acc2[2 * t + 1], v2b, p2);
        }
    }

    const float inv = 1.f / l;
    const int obase = (b * SS + qg) * 1024 + h * 64 + half * 32;
    #pragma unroll
    for (int t = 0; t < 16; t++) {
        float x0, x1;
        UNPACK2(x0, x1, acc2[t]);
        x0 *= inv; x1 *= inv;
        __nv_bfloat16 h0 = __float2bfloat16(x0), h1 = __float2bfloat16(x1);
        __nv_bfloat16 l0 = __float2bfloat16(x0 - __bfloat162float(h0));
        __nv_bfloat16 l1 = __float2bfloat16(x1 - __bfloat162float(h1));
        __nv_bfloat162 H = __halves2bfloat162(h0, h1);
        __nv_bfloat162 L = __halves2bfloat162(l0, l1);
        *(uint32_t*)&g_ahi[obase + 2 * t] = *(uint32_t*)&H;
        *(uint32_t*)&g_alo[obase + 2 * t] = *(uint32_t*)&L;
    }
}

// ---------------------------------------------------------------------------
extern "C" void kernel_launch(void* const* d_in, const int* in_sizes, int n_in,
                              void* d_out, int out_size)
{
    const float* x  = (const float*)d_in[0];
    const float* fc = (const float*)d_in[1];
    const float* fs = (const float*)d_in[2];
    const float* wq = (const float*)d_in[3];
    const float* wk = (const float*)d_in[4];
    const float* wv = (const float*)d_in[5];
    const float* wo = (const float*)d_in[6];
    float* out = (float*)d_out;

    __nv_bfloat16 *xhi, *xlo, *wthi, *wtlo, *wohi, *wolo, *ahi, *alo;
    cudaGetSymbolAddress((void**)&xhi,  g_xhi);
    cudaGetSymbolAddress((void**)&xlo,  g_xlo);
    cudaGetSymbolAddress((void**)&wthi, g_wt_hi);
    cudaGetSymbolAddress((void**)&wtlo, g_wt_lo);
    cudaGetSymbolAddress((void**)&wohi, g_wo_hi);
    cudaGetSymbolAddress((void**)&wolo, g_wo_lo);
    cudaGetSymbolAddress((void**)&ahi,  g_ahi);
    cudaGetSymbolAddress((void**)&alo,  g_alo);

    // input conversions
    split_kernel<<<MM * DD / 1024, 256>>>(x, xhi, xlo);
    transpose_split_kernel<<<dim3(32, 32), dim3(32, 8)>>>(wq, 1024, wthi, wtlo, 0);
    transpose_split_kernel<<<dim3(8, 32),  dim3(32, 8)>>>(wk, 256,  wthi, wtlo, 1024);
    transpose_split_kernel<<<dim3(8, 32),  dim3(32, 8)>>>(wv, 256,  wthi, wtlo, 1280);
    transpose_split_kernel<<<dim3(32, 32), dim3(32, 8)>>>(wo, 1024, wohi, wolo, 0);

    // QKV projection + RoPE (HMMA)
    mma_gemm_kernel<<<dim3(12, 32), 256>>>(xhi, xlo, wthi, wtlo, fc, fs, nullptr, 0);
    // attention
    attn_kernel<<<dim3(SS / 16, KVHn, BB), 128>>>();
    // output projection (HMMA)
    mma_gemm_kernel<<<dim3(8, 32), 256>>>(ahi, alo, wohi, wolo, nullptr, nullptr, out, 1);
}